// round 5
// baseline (speedup 1.0000x reference)
#include <cuda_runtime.h>
#include <cuda_bf16.h>
#include <math.h>

#define N_NODES 100000
#define N_EDGES 3200000
#define LD      6
#define HID     16
#define LL      8
#define DIN     24
#define EPS     1e-6f

#define EB ((N_EDGES + 255) / 256)
#define NB ((N_NODES + 255) / 256)

// ---------------- scratch (device globals; no allocations allowed) ----------
__device__ int2   g_eidx[N_EDGES];       // packed (src, dst) int32
__device__ float  g_deg [N_NODES];
__device__ float  g_rdeg[N_NODES];
__device__ float2 g_agg [N_NODES * 3];   // 6 floats per node, 8B-aligned for red.v2
__device__ float4 g_S   [N_NODES * 4];   // 16 floats per node: src-role precompute
__device__ float4 g_D   [N_NODES * 4];   // 16 floats per node: dst-role precompute (+b1)
__device__ float  g_Pfix[N_NODES];
__device__ float  g_bal [N_NODES];
__device__ double g_sum;

// ---------------- pack indices + degree --------------------------------------
__global__ void __launch_bounds__(256) prep_edges_i32(const int* __restrict__ ei) {
    int e = blockIdx.x * 256 + threadIdx.x;
    if (e >= N_EDGES) return;
    int s = ei[e];
    int d = ei[N_EDGES + e];
    g_eidx[e] = make_int2(s, d);
    atomicAdd(&g_deg[d], 1.0f);
}

__global__ void __launch_bounds__(256) prep_edges_i64(const long long* __restrict__ ei) {
    int e = blockIdx.x * 256 + threadIdx.x;
    if (e >= N_EDGES) return;
    int s = (int)ei[e];
    int d = (int)ei[N_EDGES + e];
    g_eidx[e] = make_int2(s, d);
    atomicAdd(&g_deg[d], 1.0f);
}

// ---------------- node kernel ------------------------------------------------
// mode 0: prep  (X := 0, compute rdeg, write S/D for layer lnext=0)
// mode 1: mid   (X := relu(agg*rdeg), write S/D for layer lnext)
// mode 2: last  (X := relu(agg*rdeg), compute P, Pfix, bal-init)
__global__ void __launch_bounds__(256) node_kernel(
    const float* __restrict__ x,
    const float* __restrict__ W1, const float* __restrict__ b1,
    const float* __restrict__ Wf, const float* __restrict__ bf,
    float* __restrict__ outP, int lnext, int mode)
{
    __shared__ float sW1[DIN * HID];
    __shared__ float sb1[HID];
    __shared__ float sWf[LD];
    __shared__ float sbf;
    int t = threadIdx.x;
    if (mode != 2) {
        for (int i = t; i < DIN * HID; i += 256) sW1[i] = W1[lnext * DIN * HID + i];
        if (t < HID) sb1[t] = b1[lnext * HID + t];
    } else {
        if (t < LD) sWf[t] = Wf[t];
        if (t == 0) sbf = bf[0];
    }
    __syncthreads();

    int n = blockIdx.x * 256 + t;
    if (n >= N_NODES) return;

    float X[LD];
    if (mode == 0) {
        float rd = 1.0f / fmaxf(g_deg[n], 1.0f);
        g_rdeg[n] = rd;
        #pragma unroll
        for (int i = 0; i < LD; i++) X[i] = 0.0f;
    } else {
        float rd = g_rdeg[n];
        const float* ag = (const float*)g_agg + (size_t)n * LD;
        #pragma unroll
        for (int i = 0; i < LD; i++) X[i] = fmaxf(ag[i] * rd, 0.0f);
    }

    if (mode == 2) {
        float p = sbf;
        #pragma unroll
        for (int i = 0; i < LD; i++) p += X[i] * sWf[i];
        p = fmaxf(p, 0.0f);
        outP[n] = p;
        float4 xv = ((const float4*)x)[n];
        g_Pfix[n] = (xv.w != 0.0f) ? xv.w : p;
        g_bal[n]  = xv.x;   // inj
        return;
    }

    float4 xv = ((const float4*)x)[n];
    float sv[HID], dv[HID];
    #pragma unroll
    for (int j = 0; j < HID; j++) {
        float a = X[0]*sW1[0*HID+j] + X[1]*sW1[1*HID+j] + X[2]*sW1[2*HID+j]
                + X[3]*sW1[3*HID+j] + X[4]*sW1[4*HID+j] + X[5]*sW1[5*HID+j];
        a += xv.x*sW1[12*HID+j] + xv.y*sW1[13*HID+j] + xv.z*sW1[14*HID+j] + xv.w*sW1[15*HID+j];
        float c = sb1[j]
                + X[0]*sW1[6*HID+j] + X[1]*sW1[7*HID+j] + X[2]*sW1[8*HID+j]
                + X[3]*sW1[9*HID+j] + X[4]*sW1[10*HID+j] + X[5]*sW1[11*HID+j];
        c += xv.x*sW1[16*HID+j] + xv.y*sW1[17*HID+j] + xv.z*sW1[18*HID+j] + xv.w*sW1[19*HID+j];
        sv[j] = a; dv[j] = c;
    }
    float4* Sp = &g_S[(size_t)n * 4];
    float4* Dp = &g_D[(size_t)n * 4];
    #pragma unroll
    for (int q = 0; q < 4; q++) {
        Sp[q] = make_float4(sv[q*4+0], sv[q*4+1], sv[q*4+2], sv[q*4+3]);
        Dp[q] = make_float4(dv[q*4+0], dv[q*4+1], dv[q*4+2], dv[q*4+3]);
    }
}

// ---------------- edge kernel ------------------------------------------------
__device__ __forceinline__ void red2(float2* p, float a, float b) {
    asm volatile("red.global.add.v2.f32 [%0], {%1, %2};" :: "l"(p), "f"(a), "f"(b) : "memory");
}

__global__ void __launch_bounds__(256) edge_kernel(
    const float4* __restrict__ ea4,
    const float* __restrict__ W1,
    const float* __restrict__ W2,
    const float* __restrict__ b2,
    int l)
{
    __shared__ float sW1e[4 * HID];   // edge_attr rows of W1 (rows 20..23)
    __shared__ float sW2 [HID * LD];
    __shared__ float sb2 [LD];
    int t = threadIdx.x;
    if (t < 4 * HID)                       sW1e[t]        = W1[l * DIN * HID + 20 * HID + t];
    else if (t < 4 * HID + HID * LD)       sW2[t - 64]    = W2[l * HID * LD + (t - 64)];
    else if (t < 4 * HID + HID * LD + LD)  sb2[t - 160]   = b2[l * LD + (t - 160)];
    __syncthreads();

    int e = blockIdx.x * 256 + t;
    if (e >= N_EDGES) return;

    int2 sd = g_eidx[e];
    float4 ea = ea4[e];

    const float4* Sp = &g_S[(size_t)sd.x * 4];
    const float4* Dp = &g_D[(size_t)sd.y * 4];

    float h[HID];
    #pragma unroll
    for (int q = 0; q < 4; q++) {
        float4 u = Sp[q];
        float4 w = Dp[q];
        h[q*4+0] = u.x + w.x; h[q*4+1] = u.y + w.y;
        h[q*4+2] = u.z + w.z; h[q*4+3] = u.w + w.w;
    }
    #pragma unroll
    for (int j = 0; j < HID; j++) {
        float v = h[j];
        v += ea.x * sW1e[0*HID + j];
        v += ea.y * sW1e[1*HID + j];
        v += ea.z * sW1e[2*HID + j];
        v += ea.w * sW1e[3*HID + j];
        h[j] = fmaxf(v, 0.0f);
    }

    float m0 = sb2[0], m1 = sb2[1], m2 = sb2[2], m3 = sb2[3], m4 = sb2[4], m5 = sb2[5];
    #pragma unroll
    for (int i = 0; i < HID; i++) {
        float hi = h[i];
        m0 += hi * sW2[i*LD + 0];
        m1 += hi * sW2[i*LD + 1];
        m2 += hi * sW2[i*LD + 2];
        m3 += hi * sW2[i*LD + 3];
        m4 += hi * sW2[i*LD + 4];
        m5 += hi * sW2[i*LD + 5];
    }

    float2* ap = &g_agg[(size_t)sd.y * 3];
    red2(ap + 0, m0, m1);
    red2(ap + 1, m2, m3);
    red2(ap + 2, m4, m5);
}

// ---------------- flows + balance -------------------------------------------
__global__ void __launch_bounds__(256) flows_kernel(
    const float4* __restrict__ ea4,
    float* __restrict__ out_flows)
{
    int e = blockIdx.x * 256 + threadIdx.x;
    if (e >= N_EDGES) return;
    int2 sd = g_eidx[e];
    float ps = g_Pfix[sd.x];
    float pd = g_Pfix[sd.y];
    float dp2 = ps * ps - pd * pd;
    float k = ea4[e].x;
    float sg = (dp2 > 0.0f) ? 1.0f : ((dp2 < 0.0f) ? -1.0f : 0.0f);
    float f = sg * sqrtf(fabsf(dp2) / k + EPS);
    out_flows[e] = f;
    atomicAdd(&g_bal[sd.y], f);
    atomicAdd(&g_bal[sd.x], -f);
}

// ---------------- imbalance reduction ----------------------------------------
__global__ void __launch_bounds__(256) reduce_kernel() {
    __shared__ double sh[256];
    int n = blockIdx.x * 256 + threadIdx.x;
    double v = 0.0;
    if (n < N_NODES) {
        double b = (double)g_bal[n];
        v = b * b;
    }
    sh[threadIdx.x] = v;
    __syncthreads();
    for (int s = 128; s > 0; s >>= 1) {
        if (threadIdx.x < s) sh[threadIdx.x] += sh[threadIdx.x + s];
        __syncthreads();
    }
    if (threadIdx.x == 0) atomicAdd(&g_sum, sh[0]);
}

__global__ void final_kernel(float* __restrict__ out) {
    out[0] = (float)sqrt(g_sum);
}

// ---------------- launch ------------------------------------------------------
extern "C" void kernel_launch(void* const* d_in, const int* in_sizes, int n_in,
                              void* d_out, int out_size)
{
    const float*  x   = (const float*)d_in[0];
    const float4* ea4 = (const float4*)d_in[1];
    const void*   ei  = d_in[2];
    const float*  W1  = (const float*)d_in[3];
    const float*  b1  = (const float*)d_in[4];
    const float*  W2  = (const float*)d_in[5];
    const float*  b2  = (const float*)d_in[6];
    const float*  Wf  = (const float*)d_in[7];
    const float*  bf  = (const float*)d_in[8];
    float* out = (float*)d_out;

    static void *p_deg = nullptr, *p_agg = nullptr, *p_sum = nullptr;
    if (!p_deg) {
        cudaGetSymbolAddress(&p_deg, g_deg);
        cudaGetSymbolAddress(&p_agg, g_agg);
        cudaGetSymbolAddress(&p_sum, g_sum);
    }

    cudaMemsetAsync(p_deg, 0, N_NODES * sizeof(float));
    cudaMemsetAsync(p_sum, 0, sizeof(double));

    // Dtype-adaptive edge_index unpack: element count 2*E means 4-byte int32
    // elements; a larger count means the buffer holds 8-byte int64 elements.
    if (in_sizes[2] == 2 * N_EDGES) {
        prep_edges_i32<<<EB, 256>>>((const int*)ei);
    } else {
        prep_edges_i64<<<EB, 256>>>((const long long*)ei);
    }
    node_kernel<<<NB, 256>>>(x, W1, b1, Wf, bf, out, 0, 0);      // prep: rdeg + S/D for l=0

    for (int l = 0; l < LL; l++) {
        cudaMemsetAsync(p_agg, 0, N_NODES * 3 * sizeof(float2));
        edge_kernel<<<EB, 256>>>(ea4, W1, W2, b2, l);
        node_kernel<<<NB, 256>>>(x, W1, b1, Wf, bf, out, l + 1, (l == LL - 1) ? 2 : 1);
    }

    flows_kernel<<<EB, 256>>>(ea4, out + N_NODES);
    reduce_kernel<<<NB, 256>>>();
    final_kernel<<<1, 1>>>(out + N_NODES + N_EDGES);
}